// round 12
// baseline (speedup 1.0000x reference)
#include <cuda_runtime.h>
#include <cuda_bf16.h>
#include <cstdint>

#define NBLK 296            // 148 SMs x 2 resident CTAs
#define NCONS 512           // consumer threads (16 warps)
#define THREADS 544         // + 1 producer warp
#define STAGE_BYTES 16384
#define STAGE_QUADS 1024
#define NSTAGE 4
#define DSMEM_BYTES (NSTAGE * STAGE_BYTES)

__device__ float        g_partials[NBLK];
__device__ unsigned int g_done = 0;

typedef unsigned long long u64;

__device__ __forceinline__ u64 pk2(float lo, float hi) {
    u64 r;
    asm("mov.b64 %0, {%1, %2};" : "=l"(r) : "f"(lo), "f"(hi));
    return r;
}
__device__ __forceinline__ void upk2(u64 v, float& lo, float& hi) {
    asm("mov.b64 {%0, %1}, %2;" : "=f"(lo), "=f"(hi) : "l"(v));
}
__device__ __forceinline__ u64 ffma2(u64 a, u64 b, u64 c) {
    u64 d;
    asm("fma.rn.f32x2 %0, %1, %2, %3;" : "=l"(d) : "l"(a), "l"(b), "l"(c));
    return d;
}
__device__ __forceinline__ u64 fmul2(u64 a, u64 b) {
    u64 d;
    asm("mul.rn.f32x2 %0, %1, %2;" : "=l"(d) : "l"(a), "l"(b));
    return d;
}
__device__ __forceinline__ u64 fadd2(u64 a, u64 b) {
    u64 d;
    asm("add.rn.f32x2 %0, %1, %2;" : "=l"(d) : "l"(a), "l"(b));
    return d;
}
__device__ __forceinline__ float ex2a(float x) {
    float y;
    asm("ex2.approx.f32 %0, %1;" : "=f"(y) : "f"(x));
    return y;
}
__device__ __forceinline__ uint32_t cvta_s(const void* p) {
    uint32_t a;
    asm("{ .reg .u64 t; cvta.to.shared.u64 t, %1; cvt.u32.u64 %0, t; }"
        : "=r"(a) : "l"(p));
    return a;
}
__device__ __forceinline__ void mbar_init(uint32_t mb, uint32_t cnt) {
    asm volatile("mbarrier.init.shared.b64 [%0], %1;" :: "r"(mb), "r"(cnt) : "memory");
}
__device__ __forceinline__ void mbar_expect_tx(uint32_t mb, uint32_t bytes) {
    asm volatile("mbarrier.arrive.expect_tx.shared.b64 _, [%0], %1;"
                 :: "r"(mb), "r"(bytes) : "memory");
}
__device__ __forceinline__ void mbar_arrive_cnt(uint32_t mb, uint32_t cnt) {
    asm volatile("mbarrier.arrive.shared.b64 _, [%0], %1;"
                 :: "r"(mb), "r"(cnt) : "memory");
}
__device__ __forceinline__ void bulk_g2s(uint32_t dst_smem, const void* src, uint32_t bytes,
                                         uint32_t mb) {
    asm volatile(
        "cp.async.bulk.shared::cluster.global.mbarrier::complete_tx::bytes "
        "[%0], [%1], %2, [%3];"
        :: "r"(dst_smem), "l"(src), "r"(bytes), "r"(mb) : "memory");
}
__device__ __forceinline__ void mbar_wait(uint32_t mb, uint32_t parity) {
    asm volatile(
        "{\n\t.reg .pred P;\n\t"
        "W_%=:\n\t"
        "mbarrier.try_wait.parity.acquire.cta.shared::cta.b64 P, [%0], %1, 0x989680;\n\t"
        "@P bra.uni D_%=;\n\t"
        "bra.uni W_%=;\n\t"
        "D_%=:\n\t}"
        :: "r"(mb), "r"(parity) : "memory");
}

__global__ __launch_bounds__(THREADS, 2) void bce_kernel(
    const float* __restrict__ x,
    const int* __restrict__ tg32,   // int64 targets viewed as int pairs (LE low word)
    float* __restrict__ out,
    int B, int N, float inv_count)
{
    extern __shared__ __align__(128) char dsm[];   // NSTAGE * 16 KB ring
    float4* const sbuf = reinterpret_cast<float4*>(dsm);
    __shared__ __align__(8) unsigned long long full_store[NSTAGE];
    __shared__ __align__(8) unsigned long long empty_store[NSTAGE];

    const int n4 = N >> 2;
    const int tid = threadIdx.x;

    // log1p(y) on [0,1]: A&S 4.1.43 degree-5 poly, |err| <= 1e-5
    const u64 C0   = pk2( 0.99949556f,  0.99949556f);
    const u64 C1   = pk2(-0.49190896f, -0.49190896f);
    const u64 C2   = pk2( 0.28947478f,  0.28947478f);
    const u64 C3   = pk2(-0.13606275f, -0.13606275f);
    const u64 C4   = pk2( 0.03215845f,  0.03215845f);
    const u64 NL2E = pk2(-1.4426950408889634f, -1.4426950408889634f);
    const u64 SGN2 = 0x8000000080000000ULL;
    const u64 ABSM = 0x7FFFFFFF7FFFFFFFULL;

    u64 accP = 0ULL;   // log1p-poly sums
    u64 accA = 0ULL;   // |x| sums
    u64 accV = 0ULL;   // sign-folded x sums
    float sFix = 0.0f;

    if (n4 == 2048) {
        const int nch = B * 2;   // 16 KB chunks (half rows)
        uint32_t fmb[NSTAGE], emb[NSTAGE];
        #pragma unroll
        for (int s2 = 0; s2 < NSTAGE; s2++) {
            fmb[s2] = cvta_s(&full_store[s2]);
            emb[s2] = cvta_s(&empty_store[s2]);
        }
        const uint32_t smem = cvta_s(sbuf);

        if (tid == 0) {
            #pragma unroll
            for (int s2 = 0; s2 < NSTAGE; s2++) {
                mbar_init(fmb[s2], 1);        // completes via expect_tx bytes
                mbar_init(emb[s2], NCONS);    // 16 warps x count-32 arrivals
            }
        }
        __syncthreads();

        if (tid >= NCONS) {
            // ---------------- producer warp ----------------
            if (tid == NCONS) {
                int stage = 0, pphase = 1;    // phase 1: first empty-wait passes
                for (int g = blockIdx.x; g < nch; g += gridDim.x) {
                    mbar_wait(emb[stage], pphase);
                    const char* sp = (const char*)x
                                   + (size_t)(g >> 1) * (size_t)N * 4u
                                   + ((g & 1) ? STAGE_BYTES : 0);
                    mbar_expect_tx(fmb[stage], STAGE_BYTES);
                    bulk_g2s(smem + stage * STAGE_BYTES, sp, STAGE_BYTES, fmb[stage]);
                    if (++stage == NSTAGE) { stage = 0; pphase ^= 1; }
                }
            }
        } else {
            // ---------------- consumer warps ----------------
            int stage = 0, cphase = 0;
            for (int g = blockIdx.x; g < nch; g += gridDim.x) {
                mbar_wait(fmb[stage], cphase);

                const int row  = g >> 1;
                const int t    = tg32[row * 2];
                const int q    = t >> 2;
                const int rr   = t & 3;
                const int base = (g & 1) << 10;
                const float4* sb = sbuf + (stage << 10);

                #pragma unroll
                for (int k = 0; k < 2; k++) {
                    const int lofs = tid + (k << 9);
                    const int idx  = base + lofs;
                    const float4 v = sb[lofs];
                    const u64 v01 = pk2(v.x, v.y);
                    const u64 v23 = pk2(v.z, v.w);
                    const u64 a01 = v01 & ABSM;
                    const u64 a23 = v23 & ABSM;
                    const u64 u01 = fmul2(a01, NL2E);
                    const u64 u23 = fmul2(a23, NL2E);
                    float e0, e1, e2, e3;
                    upk2(u01, e0, e1); upk2(u23, e2, e3);
                    const u64 y01 = pk2(ex2a(e0), ex2a(e1));
                    const u64 y23 = pk2(ex2a(e2), ex2a(e3));
                    u64 p01 = ffma2(y01, C4, C3);
                    p01 = ffma2(y01, p01, C2);
                    p01 = ffma2(y01, p01, C1);
                    p01 = ffma2(y01, p01, C0);
                    accP = ffma2(y01, p01, accP);
                    u64 p23 = ffma2(y23, C4, C3);
                    p23 = ffma2(y23, p23, C2);
                    p23 = ffma2(y23, p23, C1);
                    p23 = ffma2(y23, p23, C0);
                    accP = ffma2(y23, p23, accP);
                    accA = fadd2(accA, fadd2(a01, a23));
                    const u64 flip = (idx < q) ? SGN2 : 0ULL;
                    accV = fadd2(accV, fadd2(v01 ^ flip, v23 ^ flip));
                    if (idx == q && rr > 0) {
                        float c = v.x;
                        if (rr > 1) c += v.y;
                        if (rr > 2) c += v.z;
                        sFix += c;
                    }
                }

                __syncwarp();
                if ((tid & 31) == 0) mbar_arrive_cnt(emb[stage], 32);
                if (++stage == NSTAGE) { stage = 0; cphase ^= 1; }
            }
        }
    } else {
        // generic correctness path: strided rows, plain global loads
        for (int row = blockIdx.x; row < B; row += gridDim.x) {
            const int t = tg32[row * 2];
            const int q = t >> 2;
            const int rr = t & 3;
            const float4* __restrict__ xr =
                reinterpret_cast<const float4*>(x + (size_t)row * N);
            for (int idx = tid; idx < n4; idx += THREADS) {
                const float4 v = xr[idx];
                const u64 v01 = pk2(v.x, v.y);
                const u64 v23 = pk2(v.z, v.w);
                const u64 a01 = v01 & ABSM;
                const u64 a23 = v23 & ABSM;
                const u64 u01 = fmul2(a01, NL2E);
                const u64 u23 = fmul2(a23, NL2E);
                float e0, e1, e2, e3;
                upk2(u01, e0, e1); upk2(u23, e2, e3);
                const u64 y01 = pk2(ex2a(e0), ex2a(e1));
                const u64 y23 = pk2(ex2a(e2), ex2a(e3));
                u64 p01 = ffma2(y01, C4, C3);
                p01 = ffma2(y01, p01, C2);
                p01 = ffma2(y01, p01, C1);
                p01 = ffma2(y01, p01, C0);
                accP = ffma2(y01, p01, accP);
                u64 p23 = ffma2(y23, C4, C3);
                p23 = ffma2(y23, p23, C2);
                p23 = ffma2(y23, p23, C1);
                p23 = ffma2(y23, p23, C0);
                accP = ffma2(y23, p23, accP);
                accA = fadd2(accA, fadd2(a01, a23));
                const u64 flip = (idx < q) ? SGN2 : 0ULL;
                accV = fadd2(accV, fadd2(v01 ^ flip, v23 ^ flip));
                if (idx == q && rr > 0) {
                    float c = v.x;
                    if (rr > 1) c += v.y;
                    if (rr > 2) c += v.z;
                    sFix += c;
                }
            }
        }
    }

    // s = sum( 0.5*(|x| + sign*x) + log1p(exp(-|x|)) ) - boundary_fixes
    float s;
    {
        float pa, pb, aa, ab, va, vb;
        upk2(accP, pa, pb);
        upk2(accA, aa, ab);
        upk2(accV, va, vb);
        s = 0.5f * ((aa + ab) + (va + vb)) + (pa + pb) - sFix;
    }

    // ---- block reduction (17 warps) ----
    #pragma unroll
    for (int o = 16; o > 0; o >>= 1)
        s += __shfl_xor_sync(0xFFFFFFFFu, s, o);

    __shared__ float warp_sums[17];
    const int lane = tid & 31;
    const int wid  = tid >> 5;
    if (lane == 0) warp_sums[wid] = s;
    __syncthreads();

    __shared__ bool is_last;
    if (tid < 32) {
        float v = (lane < 17) ? warp_sums[lane] : 0.0f;
        #pragma unroll
        for (int o = 16; o > 0; o >>= 1)
            v += __shfl_xor_sync(0xFFFFFFFFu, v, o);
        if (lane == 0) {
            g_partials[blockIdx.x] = v;
            __threadfence();
            unsigned int ticket = atomicAdd(&g_done, 1u);
            is_last = (ticket == gridDim.x - 1);
        }
    }
    __syncthreads();

    // ---- last block: tail reduction over all partials ----
    if (is_last) {
        __threadfence();
        float d = 0.0f;
        for (int i2 = tid; i2 < (int)gridDim.x; i2 += THREADS)
            d += g_partials[i2];

        #pragma unroll
        for (int o = 16; o > 0; o >>= 1)
            d += __shfl_xor_sync(0xFFFFFFFFu, d, o);

        if (lane == 0) warp_sums[wid] = d;
        __syncthreads();

        if (tid < 32) {
            float v = (lane < 17) ? warp_sums[lane] : 0.0f;
            #pragma unroll
            for (int o = 16; o > 0; o >>= 1)
                v += __shfl_xor_sync(0xFFFFFFFFu, v, o);
            if (lane == 0) {
                out[0] = v * inv_count;
                g_done = 0;   // reset for next graph replay
            }
        }
    }
}

extern "C" void kernel_launch(void* const* d_in, const int* in_sizes, int n_in,
                              void* d_out, int out_size)
{
    const float* x    = (const float*)d_in[0];
    const int*   tg32 = (const int*)d_in[1];
    float* out = (float*)d_out;

    const int B = in_sizes[1];
    const int N = in_sizes[0] / B;

    cudaFuncSetAttribute(bce_kernel,
                         cudaFuncAttributeMaxDynamicSharedMemorySize, DSMEM_BYTES);

    const float inv_count = (float)(1.0 / ((double)B * (double)N));
    bce_kernel<<<NBLK, THREADS, DSMEM_BYTES>>>(x, tg32, out, B, N, inv_count);
}

// round 13
// speedup vs baseline: 1.0860x; 1.0860x over previous
#include <cuda_runtime.h>
#include <cuda_bf16.h>
#include <cstdint>

#define NBLK 888          // 148 SMs x 6 resident CTAs — one persistent wave
#define STAGE_BYTES 16384
#define STAGE_QUADS 1024

__device__ float        g_partials[NBLK];
__device__ unsigned int g_done = 0;

typedef unsigned long long u64;

__device__ __forceinline__ u64 pk2(float lo, float hi) {
    u64 r;
    asm("mov.b64 %0, {%1, %2};" : "=l"(r) : "f"(lo), "f"(hi));
    return r;
}
__device__ __forceinline__ void upk2(u64 v, float& lo, float& hi) {
    asm("mov.b64 {%0, %1}, %2;" : "=f"(lo), "=f"(hi) : "l"(v));
}
__device__ __forceinline__ u64 ffma2(u64 a, u64 b, u64 c) {
    u64 d;
    asm("fma.rn.f32x2 %0, %1, %2, %3;" : "=l"(d) : "l"(a), "l"(b), "l"(c));
    return d;
}
__device__ __forceinline__ u64 fmul2(u64 a, u64 b) {
    u64 d;
    asm("mul.rn.f32x2 %0, %1, %2;" : "=l"(d) : "l"(a), "l"(b));
    return d;
}
__device__ __forceinline__ u64 fadd2(u64 a, u64 b) {
    u64 d;
    asm("add.rn.f32x2 %0, %1, %2;" : "=l"(d) : "l"(a), "l"(b));
    return d;
}
__device__ __forceinline__ float ex2a(float x) {
    float y;
    asm("ex2.approx.f32 %0, %1;" : "=f"(y) : "f"(x));
    return y;
}
__device__ __forceinline__ uint32_t cvta_s(const void* p) {
    uint32_t a;
    asm("{ .reg .u64 t; cvta.to.shared.u64 t, %1; cvt.u32.u64 %0, t; }"
        : "=r"(a) : "l"(p));
    return a;
}
__device__ __forceinline__ void mbar_init(uint32_t mb, uint32_t cnt) {
    asm volatile("mbarrier.init.shared.b64 [%0], %1;" :: "r"(mb), "r"(cnt) : "memory");
}
__device__ __forceinline__ void mbar_expect_tx(uint32_t mb, uint32_t bytes) {
    asm volatile("mbarrier.arrive.expect_tx.shared.b64 _, [%0], %1;"
                 :: "r"(mb), "r"(bytes) : "memory");
}
__device__ __forceinline__ void bulk_g2s(uint32_t dst_smem, const void* src, uint32_t bytes,
                                         uint32_t mb) {
    asm volatile(
        "cp.async.bulk.shared::cluster.global.mbarrier::complete_tx::bytes "
        "[%0], [%1], %2, [%3];"
        :: "r"(dst_smem), "l"(src), "r"(bytes), "r"(mb) : "memory");
}
__device__ __forceinline__ void mbar_wait(uint32_t mb, uint32_t parity) {
    asm volatile(
        "{\n\t.reg .pred P;\n\t"
        "W_%=:\n\t"
        "mbarrier.try_wait.parity.acquire.cta.shared::cta.b64 P, [%0], %1, 0x989680;\n\t"
        "@P bra.uni D_%=;\n\t"
        "bra.uni W_%=;\n\t"
        "D_%=:\n\t}"
        :: "r"(mb), "r"(parity) : "memory");
}

__global__ __launch_bounds__(256, 6) void bce_kernel(
    const float* __restrict__ x,
    const int* __restrict__ tg32,   // int64 targets viewed as int pairs (LE low word)
    float* __restrict__ out,
    int B, int N, float inv_count)
{
    __shared__ __align__(128) float4 sbuf[2 * STAGE_QUADS];   // 32 KB double buffer
    __shared__ __align__(8)  unsigned long long mbar_store[2];

    const int n4 = N >> 2;

    // log1p(y) on [0,1]: A&S 4.1.43 degree-5 poly, |err| <= 1e-5
    const u64 C0   = pk2( 0.99949556f,  0.99949556f);
    const u64 C1   = pk2(-0.49190896f, -0.49190896f);
    const u64 C2   = pk2( 0.28947478f,  0.28947478f);
    const u64 C3   = pk2(-0.13606275f, -0.13606275f);
    const u64 C4   = pk2( 0.03215845f,  0.03215845f);
    const u64 NL2E = pk2(-1.4426950408889634f, -1.4426950408889634f);
    const u64 HALF = pk2(0.5f, 0.5f);
    const u64 SGN2 = 0x8000000080000000ULL;
    const u64 ABSM = 0x7FFFFFFF7FFFFFFFULL;

    u64 accP = 0ULL;   // log1p-poly sums
    u64 accR = 0ULL;   // relu(w) sums
    float sFix = 0.0f; // partial boundary-quad corrections

    // softplus(x) - x*[j<t] == relu(w) + log1p(exp(-|w|)),  w = x sign-flipped iff j<t

    if (n4 == 2048) {
        const int nch = B * 2;   // 16 KB chunks over the whole matrix
        const uint32_t smem = cvta_s(sbuf);
        const uint32_t mb0  = cvta_s(&mbar_store[0]);
        const uint32_t mb1  = cvta_s(&mbar_store[1]);

        if (threadIdx.x == 0) {
            mbar_init(mb0, 1);
            mbar_init(mb1, 1);
        }
        __syncthreads();

        // prime the pipeline: chunks for local iterations 0 and 1
        if (threadIdx.x == 0) {
            const int g0 = blockIdx.x;
            if (g0 < nch) {
                const char* s0 = (const char*)(x + (size_t)(g0 >> 1) * N)
                               + ((g0 & 1) ? STAGE_BYTES : 0);
                mbar_expect_tx(mb0, STAGE_BYTES);
                bulk_g2s(smem, s0, STAGE_BYTES, mb0);
            }
            const int g1 = blockIdx.x + gridDim.x;
            if (g1 < nch) {
                const char* s1 = (const char*)(x + (size_t)(g1 >> 1) * N)
                               + ((g1 & 1) ? STAGE_BYTES : 0);
                mbar_expect_tx(mb1, STAGE_BYTES);
                bulk_g2s(smem + STAGE_BYTES, s1, STAGE_BYTES, mb1);
            }
        }

        int i = 0;
        for (int g = blockIdx.x; g < nch; g += gridDim.x, i++) {
            const int buf = i & 1;
            mbar_wait(buf ? mb1 : mb0, (i >> 1) & 1);

            const int row  = g >> 1;
            const int t    = tg32[row * 2];
            const int q    = t >> 2;
            const int rr   = t & 3;
            const int base = (g & 1) << 10;   // in-row quad index of this chunk's start
            const float4* sb = sbuf + (buf << 10);

            #pragma unroll
            for (int k = 0; k < 4; k++) {
                const int lofs = (int)threadIdx.x + (k << 8);
                const int idx  = base + lofs;
                const float4 v = sb[lofs];
                const u64 flip = (idx < q) ? SGN2 : 0ULL;
                const u64 w01 = pk2(v.x, v.y) ^ flip;
                const u64 w23 = pk2(v.z, v.w) ^ flip;
                const u64 a01 = w01 & ABSM;
                const u64 a23 = w23 & ABSM;
                // exp(-|w|)
                const u64 u01 = fmul2(a01, NL2E);
                const u64 u23 = fmul2(a23, NL2E);
                float e0, e1, e2, e3;
                upk2(u01, e0, e1); upk2(u23, e2, e3);
                const u64 y01 = pk2(ex2a(e0), ex2a(e1));
                const u64 y23 = pk2(ex2a(e2), ex2a(e3));
                // log1p poly; final FMA folds into accumulator
                u64 p01 = ffma2(y01, C4, C3);
                p01 = ffma2(y01, p01, C2);
                p01 = ffma2(y01, p01, C1);
                p01 = ffma2(y01, p01, C0);
                accP = ffma2(y01, p01, accP);
                u64 p23 = ffma2(y23, C4, C3);
                p23 = ffma2(y23, p23, C2);
                p23 = ffma2(y23, p23, C1);
                p23 = ffma2(y23, p23, C0);
                accP = ffma2(y23, p23, accP);
                // relu(w) = 0.5*(w + |w|)
                accR = ffma2(fadd2(w01, a01), HALF, accR);
                accR = ffma2(fadd2(w23, a23), HALF, accR);
                // partial boundary quad: first rr elems of quad q should have been
                // flipped but weren't (q not < q): softplus(-x)=softplus(x)-x → -sum
                if (idx == q && rr > 0) {
                    float c = v.x;
                    if (rr > 1) c += v.y;
                    if (rr > 2) c += v.z;
                    sFix += c;
                }
            }

            __syncthreads();   // all threads done with this buffer

            if (threadIdx.x == 0) {
                const int gn = g + 2 * gridDim.x;
                if (gn < nch) {
                    const char* sn = (const char*)(x + (size_t)(gn >> 1) * N)
                                   + ((gn & 1) ? STAGE_BYTES : 0);
                    const uint32_t mb = buf ? mb1 : mb0;
                    mbar_expect_tx(mb, STAGE_BYTES);
                    bulk_g2s(smem + buf * STAGE_BYTES, sn, STAGE_BYTES, mb);
                }
            }
        }
    } else {
        // generic correctness path: strided rows, plain global loads
        for (int row = blockIdx.x; row < B; row += gridDim.x) {
            const int t = tg32[row * 2];
            const int q = t >> 2;
            const int rr = t & 3;
            const float4* __restrict__ xr =
                reinterpret_cast<const float4*>(x + (size_t)row * N);
            for (int idx = threadIdx.x; idx < n4; idx += 256) {
                const float4 v = xr[idx];
                const u64 flip = (idx < q) ? SGN2 : 0ULL;
                const u64 w01 = pk2(v.x, v.y) ^ flip;
                const u64 w23 = pk2(v.z, v.w) ^ flip;
                const u64 a01 = w01 & ABSM;
                const u64 a23 = w23 & ABSM;
                const u64 u01 = fmul2(a01, NL2E);
                const u64 u23 = fmul2(a23, NL2E);
                float e0, e1, e2, e3;
                upk2(u01, e0, e1); upk2(u23, e2, e3);
                const u64 y01 = pk2(ex2a(e0), ex2a(e1));
                const u64 y23 = pk2(ex2a(e2), ex2a(e3));
                u64 p01 = ffma2(y01, C4, C3);
                p01 = ffma2(y01, p01, C2);
                p01 = ffma2(y01, p01, C1);
                p01 = ffma2(y01, p01, C0);
                accP = ffma2(y01, p01, accP);
                u64 p23 = ffma2(y23, C4, C3);
                p23 = ffma2(y23, p23, C2);
                p23 = ffma2(y23, p23, C1);
                p23 = ffma2(y23, p23, C0);
                accP = ffma2(y23, p23, accP);
                accR = ffma2(fadd2(w01, a01), HALF, accR);
                accR = ffma2(fadd2(w23, a23), HALF, accR);
                if (idx == q && rr > 0) {
                    float c = v.x;
                    if (rr > 1) c += v.y;
                    if (rr > 2) c += v.z;
                    sFix += c;
                }
            }
        }
    }

    // s = sum( relu(w) + log1p(exp(-|w|)) ) - boundary_fixes
    float s;
    {
        float pa, pb, ra, rb;
        upk2(accP, pa, pb);
        upk2(accR, ra, rb);
        s = (pa + pb) + (ra + rb) - sFix;
    }

    // ---- block reduction (8 warps) ----
    #pragma unroll
    for (int o = 16; o > 0; o >>= 1)
        s += __shfl_xor_sync(0xFFFFFFFFu, s, o);

    __shared__ float warp_sums[8];
    const int lane = threadIdx.x & 31;
    const int wid  = threadIdx.x >> 5;
    if (lane == 0) warp_sums[wid] = s;
    __syncthreads();

    __shared__ bool is_last;
    if (threadIdx.x < 32) {
        float v = (lane < 8) ? warp_sums[lane] : 0.0f;
        #pragma unroll
        for (int o = 4; o > 0; o >>= 1)
            v += __shfl_xor_sync(0xFFFFFFFFu, v, o);
        if (lane == 0) {
            g_partials[blockIdx.x] = v;
            __threadfence();
            unsigned int ticket = atomicAdd(&g_done, 1u);
            is_last = (ticket == gridDim.x - 1);
        }
    }
    __syncthreads();

    // ---- last block: tail reduction over all partials ----
    if (is_last) {
        __threadfence();
        float d = 0.0f;
        for (int i2 = threadIdx.x; i2 < (int)gridDim.x; i2 += 256)
            d += g_partials[i2];

        #pragma unroll
        for (int o = 16; o > 0; o >>= 1)
            d += __shfl_xor_sync(0xFFFFFFFFu, d, o);

        if (lane == 0) warp_sums[wid] = d;
        __syncthreads();

        if (threadIdx.x < 32) {
            float v = (lane < 8) ? warp_sums[lane] : 0.0f;
            #pragma unroll
            for (int o = 4; o > 0; o >>= 1)
                v += __shfl_xor_sync(0xFFFFFFFFu, v, o);
            if (lane == 0) {
                out[0] = v * inv_count;
                g_done = 0;   // reset for next graph replay
            }
        }
    }
}

extern "C" void kernel_launch(void* const* d_in, const int* in_sizes, int n_in,
                              void* d_out, int out_size)
{
    const float* x    = (const float*)d_in[0];
    const int*   tg32 = (const int*)d_in[1];
    float* out = (float*)d_out;

    const int B = in_sizes[1];
    const int N = in_sizes[0] / B;

    const float inv_count = (float)(1.0 / ((double)B * (double)N));
    bce_kernel<<<NBLK, 256>>>(x, tg32, out, B, N, inv_count);
}

// round 14
// speedup vs baseline: 1.0868x; 1.0007x over previous
#include <cuda_runtime.h>
#include <cuda_bf16.h>
#include <cstdint>

#define NBLK 888          // 148 SMs x 6 resident CTAs — one persistent wave
#define STAGE_BYTES 16384
#define STAGE_QUADS 1024

__device__ float        g_partials[NBLK];
__device__ unsigned int g_done = 0;

typedef unsigned long long u64;

__device__ __forceinline__ u64 pk2(float lo, float hi) {
    u64 r;
    asm("mov.b64 %0, {%1, %2};" : "=l"(r) : "f"(lo), "f"(hi));
    return r;
}
__device__ __forceinline__ void upk2(u64 v, float& lo, float& hi) {
    asm("mov.b64 {%0, %1}, %2;" : "=f"(lo), "=f"(hi) : "l"(v));
}
__device__ __forceinline__ u64 ffma2(u64 a, u64 b, u64 c) {
    u64 d;
    asm("fma.rn.f32x2 %0, %1, %2, %3;" : "=l"(d) : "l"(a), "l"(b), "l"(c));
    return d;
}
__device__ __forceinline__ u64 fmul2(u64 a, u64 b) {
    u64 d;
    asm("mul.rn.f32x2 %0, %1, %2;" : "=l"(d) : "l"(a), "l"(b));
    return d;
}
__device__ __forceinline__ float ex2a(float x) {
    float y;
    asm("ex2.approx.f32 %0, %1;" : "=f"(y) : "f"(x));
    return y;
}
__device__ __forceinline__ uint32_t cvta_s(const void* p) {
    uint32_t a;
    asm("{ .reg .u64 t; cvta.to.shared.u64 t, %1; cvt.u32.u64 %0, t; }"
        : "=r"(a) : "l"(p));
    return a;
}
__device__ __forceinline__ void mbar_init(uint32_t mb, uint32_t cnt) {
    asm volatile("mbarrier.init.shared.b64 [%0], %1;" :: "r"(mb), "r"(cnt) : "memory");
}
__device__ __forceinline__ void mbar_expect_tx(uint32_t mb, uint32_t bytes) {
    asm volatile("mbarrier.arrive.expect_tx.shared.b64 _, [%0], %1;"
                 :: "r"(mb), "r"(bytes) : "memory");
}
__device__ __forceinline__ void bulk_g2s(uint32_t dst_smem, const void* src, uint32_t bytes,
                                         uint32_t mb) {
    asm volatile(
        "cp.async.bulk.shared::cluster.global.mbarrier::complete_tx::bytes "
        "[%0], [%1], %2, [%3];"
        :: "r"(dst_smem), "l"(src), "r"(bytes), "r"(mb) : "memory");
}
__device__ __forceinline__ void mbar_wait(uint32_t mb, uint32_t parity) {
    asm volatile(
        "{\n\t.reg .pred P;\n\t"
        "W_%=:\n\t"
        "mbarrier.try_wait.parity.acquire.cta.shared::cta.b64 P, [%0], %1, 0x989680;\n\t"
        "@P bra.uni D_%=;\n\t"
        "bra.uni W_%=;\n\t"
        "D_%=:\n\t}"
        :: "r"(mb), "r"(parity) : "memory");
}

// Per-quad compute: term(x,j) = 0.5|x| + s*0.5*x + log1p(exp(-|x|)),
// s = -1 if j < t else +1.  (softplus(x) - x*[j<t] rewritten; |w|=|x|.)
__device__ __forceinline__ void quad_body(
    u64 v01, u64 v23, u64 sh2,
    u64 C0, u64 C1, u64 C2, u64 C3, u64 C4, u64 NL2E, u64 HALF, u64 ABSM,
    u64& accP, u64& accR)
{
    const u64 a01 = v01 & ABSM;
    const u64 a23 = v23 & ABSM;
    // exp(-|x|)
    const u64 u01 = fmul2(a01, NL2E);
    const u64 u23 = fmul2(a23, NL2E);
    float e0, e1, e2, e3;
    upk2(u01, e0, e1); upk2(u23, e2, e3);
    const u64 y01 = pk2(ex2a(e0), ex2a(e1));
    const u64 y23 = pk2(ex2a(e2), ex2a(e3));
    // log1p poly (A&S 4.1.43 deg-5, |err|<=1e-5); final FMA folds into acc
    u64 p01 = ffma2(y01, C4, C3);
    p01 = ffma2(y01, p01, C2);
    p01 = ffma2(y01, p01, C1);
    p01 = ffma2(y01, p01, C0);
    accP = ffma2(y01, p01, accP);
    u64 p23 = ffma2(y23, C4, C3);
    p23 = ffma2(y23, p23, C2);
    p23 = ffma2(y23, p23, C1);
    p23 = ffma2(y23, p23, C0);
    accP = ffma2(y23, p23, accP);
    // 0.5|x| + s*0.5*x  (sign carried in sh2, no bit-flips)
    accR = ffma2(a01, HALF, accR);
    accR = ffma2(a23, HALF, accR);
    accR = ffma2(v01, sh2, accR);
    accR = ffma2(v23, sh2, accR);
}

__global__ __launch_bounds__(256, 6) void bce_kernel(
    const float* __restrict__ x,
    const int* __restrict__ tg32,   // int64 targets viewed as int pairs (LE low word)
    float* __restrict__ out,
    int B, int N, float inv_count)
{
    __shared__ __align__(128) ulonglong2 sbuf[2 * STAGE_QUADS];   // 32 KB double buffer
    __shared__ __align__(8)  unsigned long long mbar_store[2];

    const int n4 = N >> 2;

    const u64 C0   = pk2( 0.99949556f,  0.99949556f);
    const u64 C1   = pk2(-0.49190896f, -0.49190896f);
    const u64 C2   = pk2( 0.28947478f,  0.28947478f);
    const u64 C3   = pk2(-0.13606275f, -0.13606275f);
    const u64 C4   = pk2( 0.03215845f,  0.03215845f);
    const u64 NL2E = pk2(-1.4426950408889634f, -1.4426950408889634f);
    const u64 HALF = pk2(0.5f, 0.5f);
    const u64 ABSM = 0x7FFFFFFF7FFFFFFFULL;

    u64 accP = 0ULL;   // log1p-poly sums
    u64 accR = 0ULL;   // 0.5|x| + s*0.5x sums
    float sFix = 0.0f; // partial boundary-quad corrections

    if (n4 == 2048) {
        const int nch = B * 2;   // 16 KB chunks over the whole matrix
        const uint32_t smem = cvta_s(sbuf);
        const uint32_t mb0  = cvta_s(&mbar_store[0]);
        const uint32_t mb1  = cvta_s(&mbar_store[1]);

        if (threadIdx.x == 0) {
            mbar_init(mb0, 1);
            mbar_init(mb1, 1);
        }
        __syncthreads();

        if (threadIdx.x == 0) {
            const int g0 = blockIdx.x;
            if (g0 < nch) {
                const char* s0 = (const char*)(x + (size_t)(g0 >> 1) * N)
                               + ((g0 & 1) ? STAGE_BYTES : 0);
                mbar_expect_tx(mb0, STAGE_BYTES);
                bulk_g2s(smem, s0, STAGE_BYTES, mb0);
            }
            const int g1 = blockIdx.x + gridDim.x;
            if (g1 < nch) {
                const char* s1 = (const char*)(x + (size_t)(g1 >> 1) * N)
                               + ((g1 & 1) ? STAGE_BYTES : 0);
                mbar_expect_tx(mb1, STAGE_BYTES);
                bulk_g2s(smem + STAGE_BYTES, s1, STAGE_BYTES, mb1);
            }
        }

        int i = 0;
        for (int g = blockIdx.x; g < nch; g += gridDim.x, i++) {
            const int buf = i & 1;
            mbar_wait(buf ? mb1 : mb0, (i >> 1) & 1);

            const int row  = g >> 1;
            const int t    = tg32[row * 2];
            const int q    = t >> 2;
            const int rr   = t & 3;
            const int base = (g & 1) << 10;
            const ulonglong2* sb = sbuf + (buf << 10);

            #pragma unroll
            for (int k = 0; k < 4; k++) {
                const int lofs = (int)threadIdx.x + (k << 8);
                const int idx  = base + lofs;
                const ulonglong2 v = sb[lofs];
                const float sh = (idx < q) ? -0.5f : 0.5f;
                const u64 sh2 = pk2(sh, sh);
                quad_body(v.x, v.y, sh2, C0, C1, C2, C3, C4, NL2E, HALF, ABSM,
                          accP, accR);
                if (idx == q && rr > 0) {   // rare: partial boundary quad → -x per elem
                    float f0, f1, f2, f3;
                    upk2(v.x, f0, f1); upk2(v.y, f2, f3);
                    float c = f0;
                    if (rr > 1) c += f1;
                    if (rr > 2) c += f2;
                    sFix += c;
                }
            }

            __syncthreads();   // buffer fully consumed

            if (threadIdx.x == 0) {
                const int gn = g + 2 * gridDim.x;
                if (gn < nch) {
                    const char* sn = (const char*)(x + (size_t)(gn >> 1) * N)
                                   + ((gn & 1) ? STAGE_BYTES : 0);
                    const uint32_t mb = buf ? mb1 : mb0;
                    mbar_expect_tx(mb, STAGE_BYTES);
                    bulk_g2s(smem + buf * STAGE_BYTES, sn, STAGE_BYTES, mb);
                }
            }
        }
    } else {
        // generic correctness path: strided rows, plain global loads
        for (int row = blockIdx.x; row < B; row += gridDim.x) {
            const int t = tg32[row * 2];
            const int q = t >> 2;
            const int rr = t & 3;
            const ulonglong2* __restrict__ xr =
                reinterpret_cast<const ulonglong2*>(x + (size_t)row * N);
            for (int idx = threadIdx.x; idx < n4; idx += 256) {
                const ulonglong2 v = xr[idx];
                const float sh = (idx < q) ? -0.5f : 0.5f;
                const u64 sh2 = pk2(sh, sh);
                quad_body(v.x, v.y, sh2, C0, C1, C2, C3, C4, NL2E, HALF, ABSM,
                          accP, accR);
                if (idx == q && rr > 0) {
                    float f0, f1, f2, f3;
                    upk2(v.x, f0, f1); upk2(v.y, f2, f3);
                    float c = f0;
                    if (rr > 1) c += f1;
                    if (rr > 2) c += f2;
                    sFix += c;
                }
            }
        }
    }

    float s;
    {
        float pa, pb, ra, rb;
        upk2(accP, pa, pb);
        upk2(accR, ra, rb);
        s = (pa + pb) + (ra + rb) - sFix;
    }

    // ---- block reduction (8 warps) ----
    #pragma unroll
    for (int o = 16; o > 0; o >>= 1)
        s += __shfl_xor_sync(0xFFFFFFFFu, s, o);

    __shared__ float warp_sums[8];
    const int lane = threadIdx.x & 31;
    const int wid  = threadIdx.x >> 5;
    if (lane == 0) warp_sums[wid] = s;
    __syncthreads();

    __shared__ bool is_last;
    if (threadIdx.x < 32) {
        float v = (lane < 8) ? warp_sums[lane] : 0.0f;
        #pragma unroll
        for (int o = 4; o > 0; o >>= 1)
            v += __shfl_xor_sync(0xFFFFFFFFu, v, o);
        if (lane == 0) {
            g_partials[blockIdx.x] = v;
            __threadfence();
            unsigned int ticket = atomicAdd(&g_done, 1u);
            is_last = (ticket == gridDim.x - 1);
        }
    }
    __syncthreads();

    // ---- last block: tail reduction over all partials ----
    if (is_last) {
        __threadfence();
        float d = 0.0f;
        for (int i2 = threadIdx.x; i2 < (int)gridDim.x; i2 += 256)
            d += g_partials[i2];

        #pragma unroll
        for (int o = 16; o > 0; o >>= 1)
            d += __shfl_xor_sync(0xFFFFFFFFu, d, o);

        if (lane == 0) warp_sums[wid] = d;
        __syncthreads();

        if (threadIdx.x < 32) {
            float v = (lane < 8) ? warp_sums[lane] : 0.0f;
            #pragma unroll
            for (int o = 4; o > 0; o >>= 1)
                v += __shfl_xor_sync(0xFFFFFFFFu, v, o);
            if (lane == 0) {
                out[0] = v * inv_count;
                g_done = 0;   // reset for next graph replay
            }
        }
    }
}

extern "C" void kernel_launch(void* const* d_in, const int* in_sizes, int n_in,
                              void* d_out, int out_size)
{
    const float* x    = (const float*)d_in[0];
    const int*   tg32 = (const int*)d_in[1];
    float* out = (float*)d_out;

    const int B = in_sizes[1];
    const int N = in_sizes[0] / B;

    const float inv_count = (float)(1.0 / ((double)B * (double)N));
    bce_kernel<<<NBLK, 256>>>(x, tg32, out, B, N, inv_count);
}